// round 14
// baseline (speedup 1.0000x reference)
#include <cuda_runtime.h>
#include <cuda_bf16.h>
#include <cstdint>
#include <math.h>

#define DIM      2048
#define VOCAB    128000
#define MTOT     2048
#define TILE_M   128
#define TILE_N   128
#define TILE_K   64
#define NTILES   (VOCAB/TILE_N)   // 1000
#define MTILES   (MTOT/TILE_M)    // 16
#define KCHUNKS  (DIM/TILE_K)     // 32

// smem layout (floats): SX [128][65], then SW [64][132]
#define SX_STRIDE 65
#define SW_STRIDE 132
#define SX_FLOATS (TILE_M * SX_STRIDE)
#define SW_FLOATS (TILE_K * SW_STRIDE)
#define SMEM_TOTAL ((SX_FLOATS + SW_FLOATS) * 4)   // 67072 bytes

// scratch (allocation-free rule: __device__ globals)
__device__ int   g_t32[MTOT];
__device__ float g_partial[(size_t)MTOT * NTILES];
__device__ float g_tgt[MTOT];

// Reference chain: f32 values (exact bf16) -> einsum f32-accum -> cast bf16
// -> /30 (bf16) -> tanh (bf16) -> *30 (bf16) -> f32.
__device__ __forceinline__ float softcap_bf16(float f) {
    float v0 = __bfloat162float(__float2bfloat16(f));
    float v1 = __bfloat162float(__float2bfloat16(v0 / 30.0f));
    float v2 = __bfloat162float(__float2bfloat16(tanhf(v1)));
    float v3 = __bfloat162float(__float2bfloat16(30.0f * v2));
    return v3;
}

__global__ void prep_targets_kernel(const int* __restrict__ tp)
{
    for (int i = threadIdx.x; i < MTOT; i += blockDim.x) {
        int v = tp[i];
        g_t32[i] = v < 0 ? 0 : (v >= VOCAB ? VOCAB - 1 : v);
    }
}

// l_t[m] = softcap(x[m] . W[t[m]]) — one warp per row, f32 inputs
__global__ void tgt_dot_kernel(const float* __restrict__ x,
                               const float* __restrict__ w)
{
    const int m    = blockIdx.x;
    const int lane = threadIdx.x;   // 32
    const float* xr = x + (size_t)m * DIM;
    const float* wr = w + (size_t)g_t32[m] * DIM;
    float s = 0.f;
    #pragma unroll 8
    for (int k = lane; k < DIM; k += 32)
        s = fmaf(xr[k], wr[k], s);
    #pragma unroll
    for (int o = 16; o; o >>= 1) s += __shfl_xor_sync(0xffffffffu, s, o);
    if (lane == 0) g_tgt[m] = softcap_bf16(s);
}

// ---------- tiled f32 GEMM + fused softcap/exp/row-sum epilogue ----------
// Thread (r2 = tid>>2, cg = tid&3) owns rows {r2, r2+64}, cols [cg*32, cg*32+32).
__global__ __launch_bounds__(256) void ce_gemm_f32(
    const float* __restrict__ xb,     // [2048, 2048]  f32
    const float* __restrict__ wb)     // [128000, 2048] f32
{
    extern __shared__ float smf[];
    float* sx = smf;                 // SX(r,k) = sx[r*65 + k]
    float* sw = smf + SX_FLOATS;     // SW(k,c) = sw[k*132 + c]

    const int tid = threadIdx.x;
    const int r2  = tid >> 2;        // 0..63
    const int cg  = tid & 3;         // 0..3

    const int m0 = blockIdx.x * TILE_M;   // mtile fast -> W slab L2 reuse
    const int n0 = blockIdx.y * TILE_N;

    float acc0[32], acc1[32];
    #pragma unroll
    for (int i = 0; i < 32; i++) { acc0[i] = 0.f; acc1[i] = 0.f; }

    const int ldrow = tid >> 1;          // 0..127
    const int ldkh  = (tid & 1) * 32;    // 0 or 32

    for (int kc = 0; kc < KCHUNKS; kc++) {
        // x tile: SX(row, kk) = x[m0+row][kc*64+kk]
        {
            const float* xs = xb + (size_t)(m0 + ldrow) * DIM + kc * TILE_K + ldkh;
            float* dst = &sx[ldrow * SX_STRIDE + ldkh];
            #pragma unroll
            for (int j = 0; j < 32; j += 4) {
                float4 v = *(const float4*)(xs + j);
                dst[j] = v.x; dst[j+1] = v.y; dst[j+2] = v.z; dst[j+3] = v.w;
            }
        }
        // w tile transposed: SW(kk, col) = w[n0+col][kc*64+kk]
        {
            const float* ws = wb + (size_t)(n0 + ldrow) * DIM + kc * TILE_K + ldkh;
            #pragma unroll
            for (int j = 0; j < 32; j += 4) {
                float4 v = *(const float4*)(ws + j);
                sw[(ldkh + j + 0) * SW_STRIDE + ldrow] = v.x;
                sw[(ldkh + j + 1) * SW_STRIDE + ldrow] = v.y;
                sw[(ldkh + j + 2) * SW_STRIDE + ldrow] = v.z;
                sw[(ldkh + j + 3) * SW_STRIDE + ldrow] = v.w;
            }
        }
        __syncthreads();

        #pragma unroll 4
        for (int kk = 0; kk < TILE_K; kk++) {
            float x0 = sx[r2 * SX_STRIDE + kk];
            float x1 = sx[(r2 + 64) * SX_STRIDE + kk];
            const float4* wr = (const float4*)&sw[kk * SW_STRIDE + cg * 32];
            #pragma unroll
            for (int c4 = 0; c4 < 8; c4++) {
                float4 wv = wr[c4];
                acc0[c4*4+0] = fmaf(x0, wv.x, acc0[c4*4+0]);
                acc0[c4*4+1] = fmaf(x0, wv.y, acc0[c4*4+1]);
                acc0[c4*4+2] = fmaf(x0, wv.z, acc0[c4*4+2]);
                acc0[c4*4+3] = fmaf(x0, wv.w, acc0[c4*4+3]);
                acc1[c4*4+0] = fmaf(x1, wv.x, acc1[c4*4+0]);
                acc1[c4*4+1] = fmaf(x1, wv.y, acc1[c4*4+1]);
                acc1[c4*4+2] = fmaf(x1, wv.z, acc1[c4*4+2]);
                acc1[c4*4+3] = fmaf(x1, wv.w, acc1[c4*4+3]);
            }
        }
        __syncthreads();
    }

    // epilogue: softcap (bf16-faithful) -> exp -> per-row partial sums
    float* rsum = smf;   // [128][4], overlays sx (safe: all reads done)
    {
        float s = 0.f;
        #pragma unroll
        for (int j = 0; j < 32; j++) s += expf(softcap_bf16(acc0[j]));
        rsum[r2 * 4 + cg] = s;
    }
    {
        float s = 0.f;
        #pragma unroll
        for (int j = 0; j < 32; j++) s += expf(softcap_bf16(acc1[j]));
        rsum[(r2 + 64) * 4 + cg] = s;
    }
    __syncthreads();
    if (tid < TILE_M) {
        float p = rsum[tid*4+0] + rsum[tid*4+1] + rsum[tid*4+2] + rsum[tid*4+3];
        g_partial[(size_t)(m0 + tid) * NTILES + blockIdx.y] = p;
    }
}

// CE[m] = log(sum_exp) - l_t
__global__ void ce_reduce_kernel(float* __restrict__ out)
{
    const int m = blockIdx.x;
    const int t = threadIdx.x;
    __shared__ double sh[256];
    const float* p = &g_partial[(size_t)m * NTILES];
    double s = 0.0;
    for (int i = t; i < NTILES; i += 256) s += (double)p[i];
    sh[t] = s;
    __syncthreads();
    #pragma unroll
    for (int o = 128; o; o >>= 1) { if (t < o) sh[t] += sh[t + o]; __syncthreads(); }
    if (t == 0) out[m] = (float)(log(sh[0]) - (double)g_tgt[m]);
}

extern "C" void kernel_launch(void* const* d_in, const int* in_sizes, int n_in,
                              void* d_out, int out_size)
{
    // order-proof dispatch by element count
    const float* x   = nullptr;
    const float* w   = nullptr;
    const int*   tgt = nullptr;
    for (int i = 0; i < n_in; i++) {
        if (in_sizes[i] == MTOT)            tgt = (const int*)d_in[i];
        else if (in_sizes[i] == MTOT * DIM) x   = (const float*)d_in[i];
        else                                 w   = (const float*)d_in[i];
    }
    float* out = (float*)d_out;

    prep_targets_kernel<<<1, 256>>>(tgt);
    tgt_dot_kernel<<<MTOT, 32>>>(x, w);

    cudaFuncSetAttribute(ce_gemm_f32,
                         cudaFuncAttributeMaxDynamicSharedMemorySize, SMEM_TOTAL);
    ce_gemm_f32<<<dim3(MTILES, NTILES), 256, SMEM_TOTAL>>>(x, w);
    ce_reduce_kernel<<<MTOT, 256>>>(out);
}

// round 15
// speedup vs baseline: 30.6370x; 30.6370x over previous
#include <cuda_runtime.h>
#include <cuda_bf16.h>
#include <cstdint>
#include <math.h>

#define DIM      2048
#define VOCAB    128000
#define MTOT     2048
#define TILE_M   128
#define TILE_N   128
#define TILE_K   64
#define NTILES   (VOCAB/TILE_N)   // 1000
#define MTILES   (MTOT/TILE_M)    // 16
#define KCHUNKS  (DIM/TILE_K)     // 32

#define SM_STRIDE   72                        // 64 + 8 pad bf16 -> 144B rows, conflict-free ldmatrix
#define TILE_BYTES  (TILE_M*SM_STRIDE*2)      // 18432
#define STAGE_BYTES (2*TILE_BYTES)            // A + B per stage = 36864
#define LUT_BYTES   (65536*2)                 // bf16 LUT = 131072
#define SMEM_TOTAL  (LUT_BYTES + 2*STAGE_BYTES)  // 204800 <= 227KB

// scratch (allocation-free rule: __device__ globals)
__device__ __nv_bfloat16 g_wb[(size_t)VOCAB * DIM];   // 512 MB bf16 W
__device__ __nv_bfloat16 g_xb[(size_t)MTOT * DIM];    // 8 MB bf16 x
__device__ __nv_bfloat16 g_lut[65536];                // exp(softcap(bf16pattern))
__device__ int   g_t32[MTOT];
__device__ float g_partial[(size_t)MTOT * NTILES];
__device__ float g_tgt[MTOT];

// Reference chain: f32 logits (exact bf16-input einsum, f32 accum) -> bf16
// -> /30 (bf16) -> tanh (bf16) -> *30 (bf16) -> f32 -> exp
__device__ __forceinline__ float softcap_bf16(float f) {
    float v0 = __bfloat162float(__float2bfloat16(f));
    float v1 = __bfloat162float(__float2bfloat16(v0 / 30.0f));
    float v2 = __bfloat162float(__float2bfloat16(tanhf(v1)));
    float v3 = __bfloat162float(__float2bfloat16(30.0f * v2));
    return v3;
}

__global__ void prep_targets_kernel(const int* __restrict__ tp)
{
    for (int i = threadIdx.x; i < MTOT; i += blockDim.x) {
        int v = tp[i];
        g_t32[i] = v < 0 ? 0 : (v >= VOCAB ? VOCAB - 1 : v);
    }
}

// exact LUT over all 65536 bf16 bit patterns of the f32 accumulator
__global__ void build_lut_kernel()
{
    int i = blockIdx.x * blockDim.x + threadIdx.x;
    if (i < 65536) {
        unsigned short u = (unsigned short)i;
        __nv_bfloat16 b = __ushort_as_bfloat16(u);
        float v0 = __bfloat162float(b);
        float v1 = __bfloat162float(__float2bfloat16(v0 / 30.0f));
        float v2 = __bfloat162float(__float2bfloat16(tanhf(v1)));
        float v3 = __bfloat162float(__float2bfloat16(30.0f * v2));
        g_lut[i] = __float2bfloat16(expf(v3));
    }
}

// f32 (exact bf16 values) -> bf16, vectorized; exact conversion
__global__ void convert_kernel(const float* __restrict__ src,
                               __nv_bfloat16* __restrict__ dst, size_t n)
{
    size_t i = ((size_t)blockIdx.x * blockDim.x + threadIdx.x) * 4;
    size_t stride = (size_t)gridDim.x * blockDim.x * 4;
    for (; i < n; i += stride) {
        float4 v = *(const float4*)(src + i);
        *(__nv_bfloat162*)(dst + i)     = __floats2bfloat162_rn(v.x, v.y);
        *(__nv_bfloat162*)(dst + i + 2) = __floats2bfloat162_rn(v.z, v.w);
    }
}

// l_t[m] = softcap(x[m] . W[t[m]]) — f32 inputs, exact chain (validated R14)
__global__ void tgt_dot_kernel(const float* __restrict__ x,
                               const float* __restrict__ w)
{
    const int m    = blockIdx.x;
    const int lane = threadIdx.x;
    const float* xr = x + (size_t)m * DIM;
    const float* wr = w + (size_t)g_t32[m] * DIM;
    float s = 0.f;
    #pragma unroll 8
    for (int k = lane; k < DIM; k += 32)
        s = fmaf(xr[k], wr[k], s);
    #pragma unroll
    for (int o = 16; o; o >>= 1) s += __shfl_xor_sync(0xffffffffu, s, o);
    if (lane == 0) g_tgt[m] = softcap_bf16(s);
}

// ---------- bf16 HMMA GEMM + LUT sum-exp epilogue ----------
__global__ __launch_bounds__(256) void ce_gemm_mma(
    const __nv_bfloat16* __restrict__ xb,   // g_xb [2048,2048]
    const __nv_bfloat16* __restrict__ wb)   // g_wb [128000,2048]
{
    extern __shared__ char smem[];
    const int tid  = threadIdx.x;
    const int lane = tid & 31;
    const int warp = tid >> 5;
    const int wm   = warp >> 2;   // 0..1 (64 rows each)
    const int wn   = warp & 3;    // 0..3 (32 cols each)

    const int m0 = blockIdx.x * TILE_M;   // x-fast -> W slab L2 reuse
    const int n0 = blockIdx.y * TILE_N;

    // stage LUT into smem (65536 bf16 = 8192 x int4)
    {
        const int4* src = (const int4*)g_lut;
        int4* dst = (int4*)smem;
        #pragma unroll
        for (int i = tid; i < 8192; i += 256) dst[i] = src[i];
    }
    const __nv_bfloat16* slut = (const __nv_bfloat16*)smem;

    float acc[4][4][4];
    #pragma unroll
    for (int i = 0; i < 4; i++)
        #pragma unroll
        for (int j = 0; j < 4; j++)
            #pragma unroll
            for (int k = 0; k < 4; k++) acc[i][j][k] = 0.f;

    const uint32_t smem_u32 = (uint32_t)__cvta_generic_to_shared(smem);

    auto load_tiles = [&](int kc, int s) {
        const uint32_t abase = smem_u32 + LUT_BYTES + s * STAGE_BYTES;
        const uint32_t bbase = abase + TILE_BYTES;
        #pragma unroll
        for (int it = 0; it < 4; it++) {
            int chunk = tid + it * 256;      // 0..1023
            int row   = chunk >> 3;          // 0..127
            int c16   = chunk & 7;           // 16B chunk in row
            uint32_t soff = (uint32_t)(row * SM_STRIDE + c16 * 8) * 2;
            const void* ga = xb + (size_t)(m0 + row) * DIM + kc * TILE_K + c16 * 8;
            asm volatile("cp.async.cg.shared.global [%0], [%1], 16;\n"
                         :: "r"(abase + soff), "l"(ga));
            const void* gb = wb + (size_t)(n0 + row) * DIM + kc * TILE_K + c16 * 8;
            asm volatile("cp.async.cg.shared.global [%0], [%1], 16;\n"
                         :: "r"(bbase + soff), "l"(gb));
        }
        asm volatile("cp.async.commit_group;\n");
    };

    auto compute = [&](int s) {
        const uint32_t abase = smem_u32 + LUT_BYTES + s * STAGE_BYTES;
        const uint32_t bbase = abase + TILE_BYTES;
        #pragma unroll
        for (int ks = 0; ks < 4; ks++) {
            uint32_t a[4][4];
            {
                uint32_t arow = (uint32_t)(wm * 64 + (lane & 7) + ((lane >> 3) & 1) * 8);
                uint32_t acol = (uint32_t)(ks * 16 + ((lane >> 4) & 1) * 8);
                #pragma unroll
                for (int mi = 0; mi < 4; mi++) {
                    uint32_t addr = abase + ((arow + mi * 16) * SM_STRIDE + acol) * 2;
                    asm volatile("ldmatrix.sync.aligned.m8n8.x4.shared.b16 {%0,%1,%2,%3}, [%4];\n"
                                 : "=r"(a[mi][0]), "=r"(a[mi][1]), "=r"(a[mi][2]), "=r"(a[mi][3])
                                 : "r"(addr));
                }
            }
            uint32_t b[4][2];
            {
                uint32_t brow = (uint32_t)(wn * 32 + (lane & 7));
                uint32_t bcol = (uint32_t)(ks * 16 + ((lane >> 3) & 1) * 8);
                #pragma unroll
                for (int ni = 0; ni < 4; ni++) {
                    uint32_t addr = bbase + ((brow + ni * 8) * SM_STRIDE + bcol) * 2;
                    asm volatile("ldmatrix.sync.aligned.m8n8.x2.shared.b16 {%0,%1}, [%2];\n"
                                 : "=r"(b[ni][0]), "=r"(b[ni][1]) : "r"(addr));
                }
            }
            #pragma unroll
            for (int mi = 0; mi < 4; mi++)
                #pragma unroll
                for (int ni = 0; ni < 4; ni++) {
                    asm volatile(
                        "mma.sync.aligned.m16n8k16.row.col.f32.bf16.bf16.f32 "
                        "{%0,%1,%2,%3}, {%4,%5,%6,%7}, {%8,%9}, {%0,%1,%2,%3};\n"
                        : "+f"(acc[mi][ni][0]), "+f"(acc[mi][ni][1]),
                          "+f"(acc[mi][ni][2]), "+f"(acc[mi][ni][3])
                        : "r"(a[mi][0]), "r"(a[mi][1]), "r"(a[mi][2]), "r"(a[mi][3]),
                          "r"(b[ni][0]), "r"(b[ni][1]));
                }
        }
    };

    load_tiles(0, 0);
    #pragma unroll 1
    for (int kc = 0; kc < KCHUNKS; kc++) {
        if (kc + 1 < KCHUNKS) {
            load_tiles(kc + 1, (kc + 1) & 1);
            asm volatile("cp.async.wait_group 1;\n");
        } else {
            asm volatile("cp.async.wait_group 0;\n");
        }
        __syncthreads();
        compute(kc & 1);
        __syncthreads();
    }

    // epilogue: LUT(exp(softcap(bf16(acc)))) -> per-row partial sums
    float* rs = (float*)(smem + LUT_BYTES);   // overlays tile stages
    const int gid = lane >> 2;
    const int tq  = lane & 3;

    #pragma unroll
    for (int mi = 0; mi < 4; mi++) {
        #pragma unroll
        for (int half = 0; half < 2; half++) {
            int r = wm * 64 + mi * 16 + gid + half * 8;   // local row
            float s = 0.f;
            #pragma unroll
            for (int ni = 0; ni < 4; ni++) {
                #pragma unroll
                for (int e = 0; e < 2; e++) {
                    unsigned short key =
                        __bfloat16_as_ushort(__float2bfloat16(acc[mi][ni][half * 2 + e]));
                    s += __bfloat162float(slut[key]);
                }
            }
            s += __shfl_xor_sync(0xffffffffu, s, 1);
            s += __shfl_xor_sync(0xffffffffu, s, 2);
            if (tq == 0) rs[r * 4 + wn] = s;
        }
    }
    __syncthreads();
    if (tid < TILE_M) {
        float p = rs[tid*4+0] + rs[tid*4+1] + rs[tid*4+2] + rs[tid*4+3];
        g_partial[(size_t)(m0 + tid) * NTILES + blockIdx.y] = p;
    }
}

// CE[m] = log(sum_exp) - l_t
__global__ void ce_reduce_kernel(float* __restrict__ out)
{
    const int m = blockIdx.x;
    const int t = threadIdx.x;
    __shared__ double sh[256];
    const float* p = &g_partial[(size_t)m * NTILES];
    double s = 0.0;
    for (int i = t; i < NTILES; i += 256) s += (double)p[i];
    sh[t] = s;
    __syncthreads();
    #pragma unroll
    for (int o = 128; o; o >>= 1) { if (t < o) sh[t] += sh[t + o]; __syncthreads(); }
    if (t == 0) out[m] = (float)(log(sh[0]) - (double)g_tgt[m]);
}

extern "C" void kernel_launch(void* const* d_in, const int* in_sizes, int n_in,
                              void* d_out, int out_size)
{
    const float* x   = nullptr;
    const float* w   = nullptr;
    const int*   tgt = nullptr;
    for (int i = 0; i < n_in; i++) {
        if (in_sizes[i] == MTOT)            tgt = (const int*)d_in[i];
        else if (in_sizes[i] == MTOT * DIM) x   = (const float*)d_in[i];
        else                                 w   = (const float*)d_in[i];
    }
    float* out = (float*)d_out;

    prep_targets_kernel<<<1, 256>>>(tgt);
    build_lut_kernel<<<256, 256>>>();

    __nv_bfloat16 *wb_p, *xb_p;
    cudaGetSymbolAddress((void**)&wb_p, g_wb);
    cudaGetSymbolAddress((void**)&xb_p, g_xb);
    convert_kernel<<<32768, 256>>>(w, wb_p, (size_t)VOCAB * DIM);
    convert_kernel<<<4096,  256>>>(x, xb_p, (size_t)MTOT * DIM);

    tgt_dot_kernel<<<MTOT, 32>>>(x, w);

    cudaFuncSetAttribute(ce_gemm_mma,
                         cudaFuncAttributeMaxDynamicSharedMemorySize, SMEM_TOTAL);
    ce_gemm_mma<<<dim3(MTILES, NTILES), 256, SMEM_TOTAL>>>(xb_p, wb_p);
    ce_reduce_kernel<<<MTOT, 256>>>(out);
}